// round 2
// baseline (speedup 1.0000x reference)
#include <cuda_runtime.h>
#include <cuda_bf16.h>
#include <math.h>

#define BB 4
#define SS 2048
#define DMODEL 1024
#define NH 16
#define DKV 64
#define INNER 1024            // NH * DKV
#define BS_TOT (BB * SS)      // 8192
#define NREL 4095             // 2*S - 1 relative positions

// Scratch (device-global: allocation-free per harness rules)
__device__ float g_Q[BB * SS * INNER];
__device__ float g_K[BB * SS * INNER];
__device__ float g_V[BB * SS * INNER];
__device__ float g_Ctx[BB * SS * INNER];
__device__ float g_biasTab[NH * NREL];

// ---------------------------------------------------------------------------
// Relative-position bias table: biasTab[h][rel + 2047], rel = k_pos - q_pos
// Faithful port of T5 _relative_position_bucket (bidirectional, 32 buckets,
// max_distance 128).
// ---------------------------------------------------------------------------
__global__ void bias_table_kernel(const float* __restrict__ rel_emb,
                                  float* __restrict__ biasTab) {
    int h = blockIdx.x;
    for (int idx = threadIdx.x; idx < NREL; idx += blockDim.x) {
        int rel = idx - (SS - 1);       // memory_pos - context_pos
        int n = -rel;
        int ret = 0;
        if (n < 0) { ret = 16; n = -n; }   // num_buckets//2 after halving
        int bucket;
        if (n < 8) {                        // max_exact = 8
            bucket = ret + n;
        } else {
            float v = logf((float)n / 8.0f) / logf(16.0f) * 8.0f;
            int vi = 8 + (int)v;
            if (vi > 15) vi = 15;
            bucket = ret + vi;
        }
        biasTab[h * NREL + idx] = rel_emb[bucket * NH + h];
    }
}

// ---------------------------------------------------------------------------
// SGEMM: C[M,N] = A[M,K] @ B[K,N], all row-major, M%128==N%128==K%16==0.
// 128x128 tile, BK=16, 256 threads, 8x8 per thread (split 4+4 quadrants for
// conflict-free float4 smem reads).
// ---------------------------------------------------------------------------
__global__ __launch_bounds__(256) void sgemm128(
    const float* __restrict__ A, const float* __restrict__ B,
    float* __restrict__ C, int M, int N, int K) {
    __shared__ float As[16][132];   // transposed A tile, padded
    __shared__ float Bs[16][132];
    const int tid = threadIdx.x;
    const int tx = tid & 15, ty = tid >> 4;
    const int bm = blockIdx.y, bn = blockIdx.x;
    const float* Ab = A + (size_t)bm * 128 * K;
    const float* Bb = B + (size_t)bn * 128;

    float acc[8][8];
#pragma unroll
    for (int i = 0; i < 8; i++)
#pragma unroll
        for (int j = 0; j < 8; j++) acc[i][j] = 0.0f;

    for (int k0 = 0; k0 < K; k0 += 16) {
        // A tile: 128 rows x 16 cols = 512 float4
#pragma unroll
        for (int i = 0; i < 2; i++) {
            int f = tid + i * 256;
            int row = f >> 2, c4 = (f & 3) * 4;
            float4 v = *(const float4*)(Ab + (size_t)row * K + k0 + c4);
            As[c4 + 0][row] = v.x;
            As[c4 + 1][row] = v.y;
            As[c4 + 2][row] = v.z;
            As[c4 + 3][row] = v.w;
        }
        // B tile: 16 rows x 128 cols = 512 float4
#pragma unroll
        for (int i = 0; i < 2; i++) {
            int f = tid + i * 256;
            int row = f >> 5, c = (f & 31) * 4;
            float4 v = *(const float4*)(Bb + (size_t)(k0 + row) * N + c);
            *(float4*)(&Bs[row][c]) = v;
        }
        __syncthreads();

#pragma unroll
        for (int k = 0; k < 16; k++) {
            float a[8], b[8];
            *(float4*)(a)     = *(const float4*)(&As[k][ty * 4]);
            *(float4*)(a + 4) = *(const float4*)(&As[k][64 + ty * 4]);
            *(float4*)(b)     = *(const float4*)(&Bs[k][tx * 4]);
            *(float4*)(b + 4) = *(const float4*)(&Bs[k][64 + tx * 4]);
#pragma unroll
            for (int i = 0; i < 8; i++)
#pragma unroll
                for (int j = 0; j < 8; j++) acc[i][j] += a[i] * b[j];
        }
        __syncthreads();
    }

    // Epilogue: 4 quadrants of 4x4, float4 stores
#pragma unroll
    for (int ih = 0; ih < 2; ih++)
#pragma unroll
        for (int i = 0; i < 4; i++) {
            size_t grow = (size_t)bm * 128 + ih * 64 + ty * 4 + i;
#pragma unroll
            for (int jh = 0; jh < 2; jh++) {
                float4 v = make_float4(acc[ih * 4 + i][jh * 4 + 0],
                                       acc[ih * 4 + i][jh * 4 + 1],
                                       acc[ih * 4 + i][jh * 4 + 2],
                                       acc[ih * 4 + i][jh * 4 + 3]);
                *(float4*)(C + grow * N + bn * 128 + jh * 64 + tx * 4) = v;
            }
        }
}

// ---------------------------------------------------------------------------
// Flash attention with T5 relative bias.
// Grid: (S/64, B*H). Block: 256 threads (16x16).
// Each block: 64 Q rows for one (b,h). Iterates 32 K/V tiles of 64 rows.
// Per-thread 4x4 outer products; online softmax with half-warp shuffles.
// Dynamic smem: Qs/Ks/Vs/Ps each [64][65] = 66,560 B.
// ---------------------------------------------------------------------------
__global__ __launch_bounds__(256) void attn_kernel(
    const float* __restrict__ Q, const float* __restrict__ K,
    const float* __restrict__ V, const float* __restrict__ biasTab,
    float* __restrict__ Ctx) {
    extern __shared__ float sm[];
    float* Qs = sm;                 // [64][65]
    float* Ks = sm + 64 * 65;
    float* Vs = sm + 2 * 64 * 65;
    float* Ps = sm + 3 * 64 * 65;
    __shared__ float bias_s[128];   // per-tile bias diagonal slice

    const int qt = blockIdx.x;      // 0..31
    const int bh = blockIdx.y;      // 0..63
    const int b = bh >> 4, h = bh & 15;
    const int tid = threadIdx.x;
    const int tx = tid & 15, ty = tid >> 4;
    const int q0 = qt * 64;
    const size_t base = (size_t)b * SS * INNER + (size_t)h * DKV;
    const float* bt = biasTab + h * NREL;

    // Load Q tile: 64 rows x 64 d = 1024 float4
    for (int f = tid; f < 1024; f += 256) {
        int row = f >> 4, c4 = (f & 15) * 4;
        float4 v = *(const float4*)(Q + base + (size_t)(q0 + row) * INNER + c4);
        float* dst = Qs + row * 65 + c4;
        dst[0] = v.x; dst[1] = v.y; dst[2] = v.z; dst[3] = v.w;
    }

    float m[4], l[4], O[4][4];
#pragma unroll
    for (int i = 0; i < 4; i++) {
        m[i] = -1e30f;
        l[i] = 0.0f;
#pragma unroll
        for (int j = 0; j < 4; j++) O[i][j] = 0.0f;
    }

    for (int kt = 0; kt < SS / 64; kt++) {
        const int k0 = kt * 64;
        __syncthreads();   // protect Ks/Vs/bias_s (prev iter) + Qs (first iter)

        // Load K and V tiles (1024 float4 each)
        for (int f = tid; f < 1024; f += 256) {
            int row = f >> 4, c4 = (f & 15) * 4;
            float4 kv = *(const float4*)(K + base + (size_t)(k0 + row) * INNER + c4);
            float* d1 = Ks + row * 65 + c4;
            d1[0] = kv.x; d1[1] = kv.y; d1[2] = kv.z; d1[3] = kv.w;
            float4 vv = *(const float4*)(V + base + (size_t)(k0 + row) * INNER + c4);
            float* d2 = Vs + row * 65 + c4;
            d2[0] = vv.x; d2[1] = vv.y; d2[2] = vv.z; d2[3] = vv.w;
        }
        // Bias slice: rel = kcol - qrow spans [k0-q0-63, k0-q0+63]
        if (tid < 127) bias_s[tid] = bt[(k0 - q0 - 63) + tid + (SS - 1)];
        __syncthreads();

        // S = Q K^T (4x4 per thread)
        float Sc[4][4];
#pragma unroll
        for (int i = 0; i < 4; i++)
#pragma unroll
            for (int j = 0; j < 4; j++) Sc[i][j] = 0.0f;
#pragma unroll 8
        for (int d = 0; d < 64; d++) {
            float qa[4], kb[4];
#pragma unroll
            for (int i = 0; i < 4; i++) qa[i] = Qs[(ty * 4 + i) * 65 + d];
#pragma unroll
            for (int j = 0; j < 4; j++) kb[j] = Ks[(tx * 4 + j) * 65 + d];
#pragma unroll
            for (int i = 0; i < 4; i++)
#pragma unroll
                for (int j = 0; j < 4; j++) Sc[i][j] += qa[i] * kb[j];
        }
        // Add relative-position bias
#pragma unroll
        for (int i = 0; i < 4; i++) {
            int di = 63 - (ty * 4 + i);
#pragma unroll
            for (int j = 0; j < 4; j++)
                Sc[i][j] += bias_s[di + tx * 4 + j];
        }

        // Online softmax per row (rows shared by 16 tx lanes = half-warp)
#pragma unroll
        for (int i = 0; i < 4; i++) {
            float mx = Sc[i][0];
#pragma unroll
            for (int j = 1; j < 4; j++) mx = fmaxf(mx, Sc[i][j]);
#pragma unroll
            for (int off = 1; off < 16; off <<= 1)
                mx = fmaxf(mx, __shfl_xor_sync(0xffffffffu, mx, off));
            float mnew = fmaxf(m[i], mx);
            float alpha = expf(m[i] - mnew);
            float psum = 0.0f;
#pragma unroll
            for (int j = 0; j < 4; j++) {
                Sc[i][j] = expf(Sc[i][j] - mnew);
                psum += Sc[i][j];
            }
#pragma unroll
            for (int off = 1; off < 16; off <<= 1)
                psum += __shfl_xor_sync(0xffffffffu, psum, off);
            l[i] = l[i] * alpha + psum;
            m[i] = mnew;
#pragma unroll
            for (int j = 0; j < 4; j++) O[i][j] *= alpha;
            // stage P to smem for PV
            float* pr = Ps + (ty * 4 + i) * 65 + tx * 4;
            pr[0] = Sc[i][0]; pr[1] = Sc[i][1]; pr[2] = Sc[i][2]; pr[3] = Sc[i][3];
        }
        __syncthreads();

        // O += P @ V (4x4 per thread: rows ty*4.., d-cols tx*4..)
#pragma unroll 4
        for (int j = 0; j < 64; j++) {
            float pa[4], vb[4];
#pragma unroll
            for (int i = 0; i < 4; i++) pa[i] = Ps[(ty * 4 + i) * 65 + j];
#pragma unroll
            for (int jj = 0; jj < 4; jj++) vb[jj] = Vs[j * 65 + tx * 4 + jj];
#pragma unroll
            for (int i = 0; i < 4; i++)
#pragma unroll
                for (int jj = 0; jj < 4; jj++) O[i][jj] += pa[i] * vb[jj];
        }
    }

    // Epilogue: normalize and store context in [b, s, h, d] layout
#pragma unroll
    for (int i = 0; i < 4; i++) {
        float inv = 1.0f / l[i];
        float4 v = make_float4(O[i][0] * inv, O[i][1] * inv,
                               O[i][2] * inv, O[i][3] * inv);
        *(float4*)(Ctx + base + (size_t)(q0 + ty * 4 + i) * INNER + tx * 4) = v;
    }
}

// ---------------------------------------------------------------------------
extern "C" void kernel_launch(void* const* d_in, const int* in_sizes, int n_in,
                              void* d_out, int out_size) {
    const float* hidden = (const float*)d_in[0];
    const float* Wq     = (const float*)d_in[1];
    const float* Wk     = (const float*)d_in[2];
    const float* Wv     = (const float*)d_in[3];
    const float* Wo     = (const float*)d_in[4];
    const float* rel    = (const float*)d_in[5];
    float* out = (float*)d_out;

    float *pQ, *pK, *pV, *pC, *pB;
    cudaGetSymbolAddress((void**)&pQ, g_Q);
    cudaGetSymbolAddress((void**)&pK, g_K);
    cudaGetSymbolAddress((void**)&pV, g_V);
    cudaGetSymbolAddress((void**)&pC, g_Ctx);
    cudaGetSymbolAddress((void**)&pB, g_biasTab);

    bias_table_kernel<<<NH, 256>>>(rel, pB);

    dim3 gproj(INNER / 128, BS_TOT / 128);
    sgemm128<<<gproj, 256>>>(hidden, Wq, pQ, BS_TOT, INNER, DMODEL);
    sgemm128<<<gproj, 256>>>(hidden, Wk, pK, BS_TOT, INNER, DMODEL);
    sgemm128<<<gproj, 256>>>(hidden, Wv, pV, BS_TOT, INNER, DMODEL);

    size_t smem = (size_t)4 * 64 * 65 * sizeof(float);   // 66,560 B
    cudaFuncSetAttribute(attn_kernel,
                         cudaFuncAttributeMaxDynamicSharedMemorySize, (int)smem);
    attn_kernel<<<dim3(SS / 64, BB * NH), 256, smem>>>(pQ, pK, pV, pB, pC);

    sgemm128<<<dim3(DMODEL / 128, BS_TOT / 128), 256>>>(pC, Wo, out,
                                                        BS_TOT, DMODEL, INNER);
}

// round 4
// speedup vs baseline: 2.2765x; 2.2765x over previous
#include <cuda_runtime.h>
#include <cuda_bf16.h>
#include <math.h>
#include <stdint.h>

#define BB 4
#define SS 2048
#define DMODEL 1024
#define NH 16
#define DKV 64
#define INNER 1024
#define BS_TOT (BB * SS)
#define NREL 4095

// ---------------- scratch (device globals: allocation-free) ----------------
__device__ __align__(256) float g_biasTab[NH * NREL];
__device__ __align__(256) __nv_bfloat16 g_Hh[BS_TOT * DMODEL];
__device__ __align__(256) __nv_bfloat16 g_Hl[BS_TOT * DMODEL];
__device__ __align__(256) __nv_bfloat16 g_Qh[BS_TOT * INNER];
__device__ __align__(256) __nv_bfloat16 g_Ql[BS_TOT * INNER];
__device__ __align__(256) __nv_bfloat16 g_Kh[BS_TOT * INNER];
__device__ __align__(256) __nv_bfloat16 g_Kl[BS_TOT * INNER];
__device__ __align__(256) __nv_bfloat16 g_Vh[BS_TOT * INNER];
__device__ __align__(256) __nv_bfloat16 g_Vl[BS_TOT * INNER];
__device__ __align__(256) __nv_bfloat16 g_Ch[BS_TOT * INNER];
__device__ __align__(256) __nv_bfloat16 g_Cl[BS_TOT * INNER];
__device__ __align__(256) __nv_bfloat16 g_WqTh[INNER * DMODEL];
__device__ __align__(256) __nv_bfloat16 g_WqTl[INNER * DMODEL];
__device__ __align__(256) __nv_bfloat16 g_WkTh[INNER * DMODEL];
__device__ __align__(256) __nv_bfloat16 g_WkTl[INNER * DMODEL];
__device__ __align__(256) __nv_bfloat16 g_WvTh[INNER * DMODEL];
__device__ __align__(256) __nv_bfloat16 g_WvTl[INNER * DMODEL];
__device__ __align__(256) __nv_bfloat16 g_WoTh[DMODEL * INNER];
__device__ __align__(256) __nv_bfloat16 g_WoTl[DMODEL * INNER];

// ---------------------------- PTX helpers ----------------------------------
__device__ __forceinline__ uint32_t smem_u32(const void* p) {
    uint32_t a;
    asm("{ .reg .u64 t; cvta.to.shared.u64 t, %1; cvt.u32.u64 %0, t; }"
        : "=r"(a) : "l"(p));
    return a;
}
__device__ __forceinline__ void cp16(uint32_t dst, const void* src) {
    asm volatile("cp.async.cg.shared.global [%0], [%1], 16;"
                 :: "r"(dst), "l"(src) : "memory");
}
__device__ __forceinline__ void cp_commit() {
    asm volatile("cp.async.commit_group;" ::: "memory");
}
__device__ __forceinline__ void cp_wait0() {
    asm volatile("cp.async.wait_group 0;" ::: "memory");
}
__device__ __forceinline__ void cp_wait1() {
    asm volatile("cp.async.wait_group 1;" ::: "memory");
}
__device__ __forceinline__ void ldmx4(uint32_t* r, uint32_t addr) {
    asm volatile("ldmatrix.sync.aligned.m8n8.x4.shared.b16 {%0,%1,%2,%3}, [%4];"
                 : "=r"(r[0]), "=r"(r[1]), "=r"(r[2]), "=r"(r[3]) : "r"(addr));
}
__device__ __forceinline__ void ldmx4t(uint32_t* r, uint32_t addr) {
    asm volatile("ldmatrix.sync.aligned.m8n8.x4.trans.shared.b16 {%0,%1,%2,%3}, [%4];"
                 : "=r"(r[0]), "=r"(r[1]), "=r"(r[2]), "=r"(r[3]) : "r"(addr));
}
__device__ __forceinline__ void mma16816(float* c, const uint32_t* a,
                                         uint32_t b0, uint32_t b1) {
    asm volatile("mma.sync.aligned.m16n8k16.row.col.f32.bf16.bf16.f32 "
                 "{%0,%1,%2,%3}, {%4,%5,%6,%7}, {%8,%9}, {%0,%1,%2,%3};"
                 : "+f"(c[0]), "+f"(c[1]), "+f"(c[2]), "+f"(c[3])
                 : "r"(a[0]), "r"(a[1]), "r"(a[2]), "r"(a[3]), "r"(b0), "r"(b1));
}
__device__ __forceinline__ void store_split2(__nv_bfloat16* Ch, __nv_bfloat16* Cl,
                                             size_t off, float x, float y) {
    __nv_bfloat16 hx = __float2bfloat16(x), hy = __float2bfloat16(y);
    __nv_bfloat16 lx = __float2bfloat16(x - __bfloat162float(hx));
    __nv_bfloat16 ly = __float2bfloat16(y - __bfloat162float(hy));
    __nv_bfloat162 ph; ph.x = hx; ph.y = hy;
    __nv_bfloat162 pl; pl.x = lx; pl.y = ly;
    *(__nv_bfloat162*)(Ch + off) = ph;
    *(__nv_bfloat162*)(Cl + off) = pl;
}

// ---------------------------------------------------------------------------
// Relative-position bias table
// ---------------------------------------------------------------------------
__global__ void bias_table_kernel(const float* __restrict__ rel_emb,
                                  float* __restrict__ biasTab) {
    int h = blockIdx.x;
    for (int idx = threadIdx.x; idx < NREL; idx += blockDim.x) {
        int rel = idx - (SS - 1);
        int n = -rel;
        int ret = 0;
        if (n < 0) { ret = 16; n = -n; }
        int bucket;
        if (n < 8) {
            bucket = ret + n;
        } else {
            float v = logf((float)n / 8.0f) / logf(16.0f) * 8.0f;
            int vi = 8 + (int)v;
            if (vi > 15) vi = 15;
            bucket = ret + vi;
        }
        biasTab[h * NREL + idx] = rel_emb[bucket * NH + h];
    }
}

// ---------------------------------------------------------------------------
// fp32 -> bf16 hi/lo split (row-major, no transpose)
// ---------------------------------------------------------------------------
__global__ __launch_bounds__(256) void split_plain(const float* __restrict__ X,
                                                   __nv_bfloat16* __restrict__ Xh,
                                                   __nv_bfloat16* __restrict__ Xl,
                                                   int n4) {
    int i = blockIdx.x * 256 + threadIdx.x;
    if (i >= n4) return;
    float4 v = ((const float4*)X)[i];
    __nv_bfloat16 h0 = __float2bfloat16(v.x), h1 = __float2bfloat16(v.y);
    __nv_bfloat16 h2 = __float2bfloat16(v.z), h3 = __float2bfloat16(v.w);
    __nv_bfloat16 l0 = __float2bfloat16(v.x - __bfloat162float(h0));
    __nv_bfloat16 l1 = __float2bfloat16(v.y - __bfloat162float(h1));
    __nv_bfloat16 l2 = __float2bfloat16(v.z - __bfloat162float(h2));
    __nv_bfloat16 l3 = __float2bfloat16(v.w - __bfloat162float(h3));
    __nv_bfloat162 ph0; ph0.x = h0; ph0.y = h1;
    __nv_bfloat162 ph1; ph1.x = h2; ph1.y = h3;
    __nv_bfloat162 pl0; pl0.x = l0; pl0.y = l1;
    __nv_bfloat162 pl1; pl1.x = l2; pl1.y = l3;
    ((__nv_bfloat162*)Xh)[2 * i]     = ph0;
    ((__nv_bfloat162*)Xh)[2 * i + 1] = ph1;
    ((__nv_bfloat162*)Xl)[2 * i]     = pl0;
    ((__nv_bfloat162*)Xl)[2 * i + 1] = pl1;
}

// ---------------------------------------------------------------------------
// Weight transpose + split: W[R,C] fp32 -> Th/Tl[C,R] bf16 (K-major).
// ---------------------------------------------------------------------------
__global__ __launch_bounds__(256) void split_transpose(const float* __restrict__ W,
                                                       __nv_bfloat16* __restrict__ Th,
                                                       __nv_bfloat16* __restrict__ Tl,
                                                       int R, int C) {
    __shared__ float t[32][33];
    int bx = blockIdx.x * 32, by = blockIdx.y * 32;
    int tx = threadIdx.x, ty = threadIdx.y;
#pragma unroll
    for (int i = 0; i < 32; i += 8)
        t[ty + i][tx] = W[(size_t)(by + ty + i) * C + bx + tx];
    __syncthreads();
#pragma unroll
    for (int i = 0; i < 32; i += 8) {
        float v = t[tx][ty + i];
        __nv_bfloat16 h = __float2bfloat16(v);
        __nv_bfloat16 l = __float2bfloat16(v - __bfloat162float(h));
        size_t o = (size_t)(bx + ty + i) * R + by + tx;
        Th[o] = h;
        Tl[o] = l;
    }
}

// ---------------------------------------------------------------------------
// Split-bf16 mma.sync GEMM: C[M,N] = A[M,K] @ BT[N,K]^T
// 128x128 tile, BK=32, 256 threads (8 warps, 2x4), 2-stage cp.async pipeline.
// Smem row stride 40 bf16 (80B) -> ldmatrix conflict-free.
// Output: f32 (split_out=0) or bf16 hi/lo split (split_out=1).
// ---------------------------------------------------------------------------
#define LDS 40
#define STG_A_L 10240
#define STG_B_H 20480
#define STG_B_L 30720
#define STG_SZ  40960

__global__ __launch_bounds__(256)
void mma_gemm(const __nv_bfloat16* __restrict__ Ah, const __nv_bfloat16* __restrict__ Al,
              const __nv_bfloat16* __restrict__ Bh, const __nv_bfloat16* __restrict__ Bl,
              float* __restrict__ Cf,
              __nv_bfloat16* __restrict__ Ch, __nv_bfloat16* __restrict__ Cl,
              int M, int N, int K, int split_out) {
    extern __shared__ __align__(128) char smem[];
    const int tid = threadIdx.x, lane = tid & 31, wid = tid >> 5;
    const int wm = wid >> 2, wn = wid & 3;
    const int rowA0 = blockIdx.y * 128, rowB0 = blockIdx.x * 128;
    const uint32_t sb = smem_u32(smem);
    const int nk = K >> 5;

    float acc[16][4];
#pragma unroll
    for (int i = 0; i < 16; i++)
#pragma unroll
        for (int j = 0; j < 4; j++) acc[i][j] = 0.0f;

    // ---- async stage loader: 4 arrays x 128 rows x 2 chunks16B ----
    auto load_stage = [&](int stage, int kc) {
        const uint32_t d0 = sb + (uint32_t)stage * STG_SZ;
        const int k0 = kc * 32;
#pragma unroll
        for (int i = 0; i < 8; i++) {
            int id = tid + i * 256;
            int arr = id >> 9;
            int rem = id & 511;
            int row = rem >> 2;
            int ch  = (rem & 3) << 4;
            uint32_t dst = d0 + arr * 10240 + row * 80 + ch;
            const __nv_bfloat16* src = (arr == 0) ? Ah : (arr == 1) ? Al
                                    : (arr == 2) ? Bh : Bl;
            int grow = ((arr < 2) ? rowA0 : rowB0) + row;
            cp16(dst, (const char*)src + ((size_t)grow * K + k0) * 2 + ch);
        }
        cp_commit();
    };

    load_stage(0, 0);

    const int rA = lane & 15;
    const int cA8 = (lane >> 4) << 3;

    for (int kc = 0; kc < nk; kc++) {
        const int s = kc & 1;
        if (kc + 1 < nk) { load_stage(s ^ 1, kc + 1); cp_wait1(); }
        else             { cp_wait0(); }
        __syncthreads();

        const uint32_t base = sb + (uint32_t)s * STG_SZ;
#pragma unroll
        for (int ks = 0; ks < 32; ks += 16) {
            uint32_t a_h[4][4], b_h[2][4], b_l[2][4];
#pragma unroll
            for (int im = 0; im < 4; im++)
                ldmx4(a_h[im], base + ((64 * wm + im * 16 + rA) * LDS + ks + cA8) * 2);
#pragma unroll
            for (int jb = 0; jb < 2; jb++) {
                uint32_t boff = ((32 * wn + jb * 16 + rA) * LDS + ks + cA8) * 2;
                ldmx4(b_h[jb], base + STG_B_H + boff);
                ldmx4(b_l[jb], base + STG_B_L + boff);
            }
#pragma unroll
            for (int im = 0; im < 4; im++)
#pragma unroll
                for (int jn = 0; jn < 4; jn++) {
                    int jb = jn >> 1, sub = jn & 1;
                    mma16816(acc[im * 4 + jn], a_h[im], b_h[jb][sub], b_h[jb][sub + 2]);
                    mma16816(acc[im * 4 + jn], a_h[im], b_l[jb][sub], b_l[jb][sub + 2]);
                }
#pragma unroll
            for (int im = 0; im < 4; im++) {
                uint32_t a_l[4];
                ldmx4(a_l, base + STG_A_L + ((64 * wm + im * 16 + rA) * LDS + ks + cA8) * 2);
#pragma unroll
                for (int jn = 0; jn < 4; jn++) {
                    int jb = jn >> 1, sub = jn & 1;
                    mma16816(acc[im * 4 + jn], a_l, b_h[jb][sub], b_h[jb][sub + 2]);
                }
            }
        }
        __syncthreads();
    }

    // ---- epilogue ----
    const int er = lane >> 2, ec = (lane & 3) << 1;
#pragma unroll
    for (int im = 0; im < 4; im++) {
        int r0 = rowA0 + 64 * wm + im * 16 + er;
#pragma unroll
        for (int jn = 0; jn < 4; jn++) {
            int c = rowB0 + 32 * wn + jn * 8 + ec;
            float* a = acc[im * 4 + jn];
            if (split_out) {
                store_split2(Ch, Cl, (size_t)r0 * N + c, a[0], a[1]);
                store_split2(Ch, Cl, (size_t)(r0 + 8) * N + c, a[2], a[3]);
            } else {
                float2 v0 = make_float2(a[0], a[1]);
                float2 v1 = make_float2(a[2], a[3]);
                *(float2*)(Cf + (size_t)r0 * N + c) = v0;
                *(float2*)(Cf + (size_t)(r0 + 8) * N + c) = v1;
            }
        }
    }
}

// ---------------------------------------------------------------------------
// Flash attention on mma.sync, split-bf16 operands, T5 relative bias.
// Grid (S/64, B*H), 256 threads (8 warps in 2x4: warp tile 32 q-rows x 16 cols).
// ---------------------------------------------------------------------------
#define AQH 0
#define AQL 9216
#define AKH 18432
#define AKL 27648
#define AVH 36864
#define AVL 46080
#define APH 55296
#define APL 64512
#define ASS 73728
#define ABIAS 91136
#define AMG 91648
#define ALG 91904
#define AAS 92160
#define ATTN_SMEM 92416
#define LQ 72     // bf16 row stride (144B)
#define LSF 68    // f32 row stride

__global__ __launch_bounds__(256)
void attn_mma(const __nv_bfloat16* __restrict__ Qh, const __nv_bfloat16* __restrict__ Ql,
              const __nv_bfloat16* __restrict__ Kh, const __nv_bfloat16* __restrict__ Kl,
              const __nv_bfloat16* __restrict__ Vh, const __nv_bfloat16* __restrict__ Vl,
              const float* __restrict__ biasTab,
              __nv_bfloat16* __restrict__ Ch, __nv_bfloat16* __restrict__ Cl) {
    extern __shared__ __align__(128) char sm[];
    const int tid = threadIdx.x, lane = tid & 31, wid = tid >> 5;
    const int wm = wid >> 2, wn = wid & 3;
    const int qt = blockIdx.x, bhi = blockIdx.y;
    const int b = bhi >> 4, h = bhi & 15;
    const int q0 = qt * 64;
    const size_t base = (size_t)b * SS * INNER + (size_t)h * DKV;
    const float* bt = biasTab + h * NREL;
    const uint32_t sb = smem_u32(sm);
    float* mgp = (float*)(sm + AMG);
    float* lgp = (float*)(sm + ALG);
    float* asp = (float*)(sm + AAS);
    float* bias = (float*)(sm + ABIAS);

    // ---- load Q tile (hi+lo): 2 arrays x 64 rows x 8 chunks16B ----
#pragma unroll
    for (int i = 0; i < 4; i++) {
        int id = tid + i * 256;
        int arr = id >> 9, rem = id & 511;
        int row = rem >> 3, ch = (rem & 7) << 4;
        const __nv_bfloat16* src = arr ? Ql : Qh;
        cp16(sb + (arr ? AQL : AQH) + row * 144 + ch,
             (const char*)src + (base + (size_t)(q0 + row) * INNER) * 2 + ch);
    }
    cp_commit();

    if (tid < 64) { mgp[tid] = -1e30f; lgp[tid] = 0.0f; }

    float oac[4][4];
#pragma unroll
    for (int i = 0; i < 4; i++)
#pragma unroll
        for (int j = 0; j < 4; j++) oac[i][j] = 0.0f;

    const int rA = lane & 15, cA8 = (lane >> 4) << 3;
    const int er = lane >> 2, ec = (lane & 3) << 1;

    for (int kt = 0; kt < SS / 64; kt++) {
        const int k0 = kt * 64;
        __syncthreads();   // K/V/P/Ss reuse safety

        // ---- async load K/V tiles (hi+lo): 4 arrays x 64 rows x 8 chunks ----
#pragma unroll
        for (int i = 0; i < 8; i++) {
            int id = tid + i * 256;
            int arr = id >> 9, rem = id & 511;
            int row = rem >> 3, ch = (rem & 7) << 4;
            const __nv_bfloat16* src = (arr == 0) ? Kh : (arr == 1) ? Kl
                                    : (arr == 2) ? Vh : Vl;
            cp16(sb + AKH + arr * 9216 + row * 144 + ch,
                 (const char*)src + (base + (size_t)(k0 + row) * INNER) * 2 + ch);
        }
        cp_commit();
        if (tid < 127) bias[tid] = bt[k0 - q0 - 63 + tid + (SS - 1)];
        cp_wait0();
        __syncthreads();

        // ---- S = Q K^T ----
        float sac[4][4];
#pragma unroll
        for (int i = 0; i < 4; i++)
#pragma unroll
            for (int j = 0; j < 4; j++) sac[i][j] = 0.0f;
#pragma unroll
        for (int ks = 0; ks < 64; ks += 16) {
            uint32_t qh[2][4], ql[2][4], kh[4], kl[4];
#pragma unroll
            for (int im = 0; im < 2; im++) {
                uint32_t aoff = ((32 * wm + im * 16 + rA) * LQ + ks + cA8) * 2;
                ldmx4(qh[im], sb + AQH + aoff);
                ldmx4(ql[im], sb + AQL + aoff);
            }
            uint32_t boff = ((16 * wn + rA) * LQ + ks + cA8) * 2;
            ldmx4(kh, sb + AKH + boff);
            ldmx4(kl, sb + AKL + boff);
#pragma unroll
            for (int im = 0; im < 2; im++)
#pragma unroll
                for (int jn = 0; jn < 2; jn++) {
                    mma16816(sac[im * 2 + jn], qh[im], kh[jn], kh[jn + 2]);
                    mma16816(sac[im * 2 + jn], qh[im], kl[jn], kl[jn + 2]);
                    mma16816(sac[im * 2 + jn], ql[im], kh[jn], kh[jn + 2]);
                }
        }
        // spill S to smem (f32)
#pragma unroll
        for (int im = 0; im < 2; im++)
#pragma unroll
            for (int jn = 0; jn < 2; jn++) {
                int r = 32 * wm + im * 16 + er;
                int c = 16 * wn + jn * 8 + ec;
                float* s4 = sac[im * 2 + jn];
                *(float2*)(sm + ASS + ((size_t)r * LSF + c) * 4) = make_float2(s4[0], s4[1]);
                *(float2*)(sm + ASS + ((size_t)(r + 8) * LSF + c) * 4) = make_float2(s4[2], s4[3]);
            }
        __syncthreads();

        // ---- softmax: row = wid*8 + (lane&7); 4 lanes/row, 16 cols each ----
        {
            int row = wid * 8 + (lane & 7);
            int j0 = (lane >> 3) << 4;
            const float* srow = (const float*)(sm + ASS) + row * LSF;
            float v[16];
            float mx = -1e30f;
#pragma unroll
            for (int j = 0; j < 16; j++) {
                v[j] = srow[j0 + j] + bias[j0 + j - row + 63];
                mx = fmaxf(mx, v[j]);
            }
            mx = fmaxf(mx, __shfl_xor_sync(0xffffffffu, mx, 8));
            mx = fmaxf(mx, __shfl_xor_sync(0xffffffffu, mx, 16));
            float mold = mgp[row];
            float mnew = fmaxf(mold, mx);
            float alpha = __expf(mold - mnew);
            float ps = 0.0f;
#pragma unroll
            for (int j = 0; j < 16; j++) {
                v[j] = __expf(v[j] - mnew);
                ps += v[j];
            }
            ps += __shfl_xor_sync(0xffffffffu, ps, 8);
            ps += __shfl_xor_sync(0xffffffffu, ps, 16);
            if ((lane & 24) == 0) {
                mgp[row] = mnew;
                lgp[row] = lgp[row] * alpha + ps;
                asp[row] = alpha;
            }
            // P -> bf16 hi/lo
#pragma unroll
            for (int j = 0; j < 16; j += 2) {
                __nv_bfloat16 h0 = __float2bfloat16(v[j]);
                __nv_bfloat16 h1 = __float2bfloat16(v[j + 1]);
                __nv_bfloat16 l0 = __float2bfloat16(v[j] - __bfloat162float(h0));
                __nv_bfloat16 l1 = __float2bfloat16(v[j + 1] - __bfloat162float(h1));
                __nv_bfloat162 ph; ph.x = h0; ph.y = h1;
                __nv_bfloat162 pl; pl.x = l0; pl.y = l1;
                *(__nv_bfloat162*)(sm + APH + ((size_t)row * LQ + j0 + j) * 2) = ph;
                *(__nv_bfloat162*)(sm + APL + ((size_t)row * LQ + j0 + j) * 2) = pl;
            }
        }
        __syncthreads();

        // ---- rescale O by alpha ----
#pragma unroll
        for (int im = 0; im < 2; im++) {
            float a0 = asp[32 * wm + im * 16 + er];
            float a1 = asp[32 * wm + im * 16 + er + 8];
#pragma unroll
            for (int jn = 0; jn < 2; jn++) {
                float* o4 = oac[im * 2 + jn];
                o4[0] *= a0; o4[1] *= a0; o4[2] *= a1; o4[3] *= a1;
            }
        }

        // ---- O += P V  (V^T fragments via ldmatrix.trans) ----
#pragma unroll
        for (int ks = 0; ks < 64; ks += 16) {
            uint32_t ph[2][4], pl[2][4], vh[4], vl[4];
#pragma unroll
            for (int im = 0; im < 2; im++) {
                uint32_t aoff = ((32 * wm + im * 16 + rA) * LQ + ks + cA8) * 2;
                ldmx4(ph[im], sb + APH + aoff);
                ldmx4(pl[im], sb + APL + aoff);
            }
            uint32_t voff = ((ks + rA) * LQ + 16 * wn + cA8) * 2;
            ldmx4t(vh, sb + AVH + voff);
            ldmx4t(vl, sb + AVL + voff);
#pragma unroll
            for (int im = 0; im < 2; im++)
#pragma unroll
                for (int jn = 0; jn < 2; jn++) {
                    // trans pairing: block0 {r0,r1}, block1 {r2,r3}
                    mma16816(oac[im * 2 + jn], ph[im], vh[jn * 2], vh[jn * 2 + 1]);
                    mma16816(oac[im * 2 + jn], ph[im], vl[jn * 2], vl[jn * 2 + 1]);
                    mma16816(oac[im * 2 + jn], pl[im], vh[jn * 2], vh[jn * 2 + 1]);
                }
        }
    }

    // ---- epilogue: normalize, split-bf16 store ----
#pragma unroll
    for (int im = 0; im < 2; im++) {
        int r = 32 * wm + im * 16 + er;
        float inv0 = 1.0f / lgp[r];
        float inv1 = 1.0f / lgp[r + 8];
#pragma unroll
        for (int jn = 0; jn < 2; jn++) {
            int c = 16 * wn + jn * 8 + ec;
            float* o4 = oac[im * 2 + jn];
            size_t o0 = base + (size_t)(q0 + r) * INNER + c;
            size_t o1 = base + (size_t)(q0 + r + 8) * INNER + c;
            store_split2(Ch, Cl, o0, o4[0] * inv0, o4[1] * inv0);
            store_split2(Ch, Cl, o1, o4[2] * inv1, o4[3] * inv1);
        }
    }
}

// ---------------------------------------------------------------------------
extern "C" void kernel_launch(void* const* d_in, const int* in_sizes, int n_in,
                              void* d_out, int out_size) {
    const float* hidden = (const float*)d_in[0];
    const float* Wq     = (const float*)d_in[1];
    const float* Wk     = (const float*)d_in[2];
    const float* Wv     = (const float*)d_in[3];
    const float* Wo     = (const float*)d_in[4];
    const float* rel    = (const float*)d_in[5];
    float* out = (float*)d_out;

    float* pB;
    __nv_bfloat16 *pHh, *pHl, *pQh, *pQl, *pKh, *pKl, *pVh, *pVl, *pCh, *pCl;
    __nv_bfloat16 *pWqTh, *pWqTl, *pWkTh, *pWkTl, *pWvTh, *pWvTl, *pWoTh, *pWoTl;
    cudaGetSymbolAddress((void**)&pB, g_biasTab);
    cudaGetSymbolAddress((void**)&pHh, g_Hh);
    cudaGetSymbolAddress((void**)&pHl, g_Hl);
    cudaGetSymbolAddress((void**)&pQh, g_Qh);
    cudaGetSymbolAddress((void**)&pQl, g_Ql);
    cudaGetSymbolAddress((void**)&pKh, g_Kh);
    cudaGetSymbolAddress((void**)&pKl, g_Kl);
    cudaGetSymbolAddress((void**)&pVh, g_Vh);
    cudaGetSymbolAddress((void**)&pVl, g_Vl);
    cudaGetSymbolAddress((void**)&pCh, g_Ch);
    cudaGetSymbolAddress((void**)&pCl, g_Cl);
    cudaGetSymbolAddress((void**)&pWqTh, g_WqTh);
    cudaGetSymbolAddress((void**)&pWqTl, g_WqTl);
    cudaGetSymbolAddress((void**)&pWkTh, g_WkTh);
    cudaGetSymbolAddress((void**)&pWkTl, g_WkTl);
    cudaGetSymbolAddress((void**)&pWvTh, g_WvTh);
    cudaGetSymbolAddress((void**)&pWvTl, g_WvTl);
    cudaGetSymbolAddress((void**)&pWoTh, g_WoTh);
    cudaGetSymbolAddress((void**)&pWoTl, g_WoTl);

    cudaFuncSetAttribute(mma_gemm,
                         cudaFuncAttributeMaxDynamicSharedMemorySize, 2 * STG_SZ);
    cudaFuncSetAttribute(attn_mma,
                         cudaFuncAttributeMaxDynamicSharedMemorySize, ATTN_SMEM);

    bias_table_kernel<<<NH, 256>>>(rel, pB);

    // operand prep
    int n4h = BS_TOT * DMODEL / 4;
    split_plain<<<n4h / 256, 256>>>(hidden, pHh, pHl, n4h);
    dim3 tgrid(DMODEL / 32, DMODEL / 32), tblk(32, 8);
    split_transpose<<<tgrid, tblk>>>(Wq, pWqTh, pWqTl, DMODEL, INNER);
    split_transpose<<<tgrid, tblk>>>(Wk, pWkTh, pWkTl, DMODEL, INNER);
    split_transpose<<<tgrid, tblk>>>(Wv, pWvTh, pWvTl, DMODEL, INNER);
    split_transpose<<<tgrid, tblk>>>(Wo, pWoTh, pWoTl, INNER, DMODEL);

    // QKV projections -> split bf16 outputs
    dim3 gproj(INNER / 128, BS_TOT / 128);
    mma_gemm<<<gproj, 256, 2 * STG_SZ>>>(pHh, pHl, pWqTh, pWqTl,
                                         nullptr, pQh, pQl, BS_TOT, INNER, DMODEL, 1);
    mma_gemm<<<gproj, 256, 2 * STG_SZ>>>(pHh, pHl, pWkTh, pWkTl,
                                         nullptr, pKh, pKl, BS_TOT, INNER, DMODEL, 1);
    mma_gemm<<<gproj, 256, 2 * STG_SZ>>>(pHh, pHl, pWvTh, pWvTl,
                                         nullptr, pVh, pVl, BS_TOT, INNER, DMODEL, 1);

    // attention -> split bf16 context
    attn_mma<<<dim3(SS / 64, BB * NH), 256, ATTN_SMEM>>>(
        pQh, pQl, pKh, pKl, pVh, pVl, pB, pCh, pCl);

    // output projection -> f32 out
    mma_gemm<<<dim3(DMODEL / 128, BS_TOT / 128), 256, 2 * STG_SZ>>>(
        pCh, pCl, pWoTh, pWoTl, out, nullptr, nullptr, BS_TOT, DMODEL, INNER, 0);
}

// round 5
// speedup vs baseline: 2.7093x; 1.1901x over previous
#include <cuda_runtime.h>
#include <cuda_bf16.h>
#include <math.h>
#include <stdint.h>

#define BB 4
#define SS 2048
#define DMODEL 1024
#define NH 16
#define DKV 64
#define INNER 1024
#define BS_TOT (BB * SS)
#define NREL 4095

// ---------------- scratch (device globals: allocation-free) ----------------
__device__ __align__(256) float g_biasTab[NH * NREL];
__device__ __align__(256) __nv_bfloat16 g_Hh[BS_TOT * DMODEL];
__device__ __align__(256) __nv_bfloat16 g_Hl[BS_TOT * DMODEL];
__device__ __align__(256) __nv_bfloat16 g_Qh[BS_TOT * INNER];
__device__ __align__(256) __nv_bfloat16 g_Ql[BS_TOT * INNER];
__device__ __align__(256) __nv_bfloat16 g_Kh[BS_TOT * INNER];
__device__ __align__(256) __nv_bfloat16 g_Kl[BS_TOT * INNER];
__device__ __align__(256) __nv_bfloat16 g_Vh[BS_TOT * INNER];
__device__ __align__(256) __nv_bfloat16 g_Vl[BS_TOT * INNER];
__device__ __align__(256) __nv_bfloat16 g_Ch[BS_TOT * INNER];
__device__ __align__(256) __nv_bfloat16 g_Cl[BS_TOT * INNER];
__device__ __align__(256) __nv_bfloat16 g_WqTh[INNER * DMODEL];
__device__ __align__(256) __nv_bfloat16 g_WqTl[INNER * DMODEL];
__device__ __align__(256) __nv_bfloat16 g_WkTh[INNER * DMODEL];
__device__ __align__(256) __nv_bfloat16 g_WkTl[INNER * DMODEL];
__device__ __align__(256) __nv_bfloat16 g_WvTh[INNER * DMODEL];
__device__ __align__(256) __nv_bfloat16 g_WvTl[INNER * DMODEL];
__device__ __align__(256) __nv_bfloat16 g_WoTh[DMODEL * INNER];
__device__ __align__(256) __nv_bfloat16 g_WoTl[DMODEL * INNER];

// ---------------------------- PTX helpers ----------------------------------
__device__ __forceinline__ uint32_t smem_u32(const void* p) {
    uint32_t a;
    asm("{ .reg .u64 t; cvta.to.shared.u64 t, %1; cvt.u32.u64 %0, t; }"
        : "=r"(a) : "l"(p));
    return a;
}
__device__ __forceinline__ void cp16(uint32_t dst, const void* src) {
    asm volatile("cp.async.cg.shared.global [%0], [%1], 16;"
                 :: "r"(dst), "l"(src) : "memory");
}
__device__ __forceinline__ void cp_commit() {
    asm volatile("cp.async.commit_group;" ::: "memory");
}
__device__ __forceinline__ void cp_wait0() {
    asm volatile("cp.async.wait_group 0;" ::: "memory");
}
__device__ __forceinline__ void cp_wait1() {
    asm volatile("cp.async.wait_group 1;" ::: "memory");
}
__device__ __forceinline__ void ldmx4(uint32_t* r, uint32_t addr) {
    asm volatile("ldmatrix.sync.aligned.m8n8.x4.shared.b16 {%0,%1,%2,%3}, [%4];"
                 : "=r"(r[0]), "=r"(r[1]), "=r"(r[2]), "=r"(r[3]) : "r"(addr));
}
__device__ __forceinline__ void ldmx4t(uint32_t* r, uint32_t addr) {
    asm volatile("ldmatrix.sync.aligned.m8n8.x4.trans.shared.b16 {%0,%1,%2,%3}, [%4];"
                 : "=r"(r[0]), "=r"(r[1]), "=r"(r[2]), "=r"(r[3]) : "r"(addr));
}
__device__ __forceinline__ void mma16816(float* c, const uint32_t* a,
                                         uint32_t b0, uint32_t b1) {
    asm volatile("mma.sync.aligned.m16n8k16.row.col.f32.bf16.bf16.f32 "
                 "{%0,%1,%2,%3}, {%4,%5,%6,%7}, {%8,%9}, {%0,%1,%2,%3};"
                 : "+f"(c[0]), "+f"(c[1]), "+f"(c[2]), "+f"(c[3])
                 : "r"(a[0]), "r"(a[1]), "r"(a[2]), "r"(a[3]), "r"(b0), "r"(b1));
}
__device__ __forceinline__ uint32_t pack_bf2(float x, float y) {
    __nv_bfloat162 p;
    p.x = __float2bfloat16(x);
    p.y = __float2bfloat16(y);
    return *(uint32_t*)&p;
}
__device__ __forceinline__ void store_split2(__nv_bfloat16* Ch, __nv_bfloat16* Cl,
                                             size_t off, float x, float y) {
    __nv_bfloat16 hx = __float2bfloat16(x), hy = __float2bfloat16(y);
    __nv_bfloat16 lx = __float2bfloat16(x - __bfloat162float(hx));
    __nv_bfloat16 ly = __float2bfloat16(y - __bfloat162float(hy));
    __nv_bfloat162 ph; ph.x = hx; ph.y = hy;
    __nv_bfloat162 pl; pl.x = lx; pl.y = ly;
    *(__nv_bfloat162*)(Ch + off) = ph;
    *(__nv_bfloat162*)(Cl + off) = pl;
}

// ---------------------------------------------------------------------------
// Relative-position bias table
// ---------------------------------------------------------------------------
__global__ void bias_table_kernel(const float* __restrict__ rel_emb,
                                  float* __restrict__ biasTab) {
    int h = blockIdx.x;
    for (int idx = threadIdx.x; idx < NREL; idx += blockDim.x) {
        int rel = idx - (SS - 1);
        int n = -rel;
        int ret = 0;
        if (n < 0) { ret = 16; n = -n; }
        int bucket;
        if (n < 8) {
            bucket = ret + n;
        } else {
            float v = logf((float)n / 8.0f) / logf(16.0f) * 8.0f;
            int vi = 8 + (int)v;
            if (vi > 15) vi = 15;
            bucket = ret + vi;
        }
        biasTab[h * NREL + idx] = rel_emb[bucket * NH + h];
    }
}

// ---------------------------------------------------------------------------
// fp32 -> bf16 hi/lo split (row-major)
// ---------------------------------------------------------------------------
__global__ __launch_bounds__(256) void split_plain(const float* __restrict__ X,
                                                   __nv_bfloat16* __restrict__ Xh,
                                                   __nv_bfloat16* __restrict__ Xl,
                                                   int n4) {
    int i = blockIdx.x * 256 + threadIdx.x;
    if (i >= n4) return;
    float4 v = ((const float4*)X)[i];
    __nv_bfloat16 h0 = __float2bfloat16(v.x), h1 = __float2bfloat16(v.y);
    __nv_bfloat16 h2 = __float2bfloat16(v.z), h3 = __float2bfloat16(v.w);
    __nv_bfloat16 l0 = __float2bfloat16(v.x - __bfloat162float(h0));
    __nv_bfloat16 l1 = __float2bfloat16(v.y - __bfloat162float(h1));
    __nv_bfloat16 l2 = __float2bfloat16(v.z - __bfloat162float(h2));
    __nv_bfloat16 l3 = __float2bfloat16(v.w - __bfloat162float(h3));
    __nv_bfloat162 ph0; ph0.x = h0; ph0.y = h1;
    __nv_bfloat162 ph1; ph1.x = h2; ph1.y = h3;
    __nv_bfloat162 pl0; pl0.x = l0; pl0.y = l1;
    __nv_bfloat162 pl1; pl1.x = l2; pl1.y = l3;
    ((__nv_bfloat162*)Xh)[2 * i]     = ph0;
    ((__nv_bfloat162*)Xh)[2 * i + 1] = ph1;
    ((__nv_bfloat162*)Xl)[2 * i]     = pl0;
    ((__nv_bfloat162*)Xl)[2 * i + 1] = pl1;
}

// ---------------------------------------------------------------------------
// Weight transpose + split: W[R,C] fp32 -> Th/Tl[C,R] bf16 (K-major)
// ---------------------------------------------------------------------------
__global__ __launch_bounds__(256) void split_transpose(const float* __restrict__ W,
                                                       __nv_bfloat16* __restrict__ Th,
                                                       __nv_bfloat16* __restrict__ Tl,
                                                       int R, int C) {
    __shared__ float t[32][33];
    int bx = blockIdx.x * 32, by = blockIdx.y * 32;
    int tx = threadIdx.x, ty = threadIdx.y;
#pragma unroll
    for (int i = 0; i < 32; i += 8)
        t[ty + i][tx] = W[(size_t)(by + ty + i) * C + bx + tx];
    __syncthreads();
#pragma unroll
    for (int i = 0; i < 32; i += 8) {
        float v = t[tx][ty + i];
        __nv_bfloat16 h = __float2bfloat16(v);
        __nv_bfloat16 l = __float2bfloat16(v - __bfloat162float(h));
        size_t o = (size_t)(bx + ty + i) * R + by + tx;
        Th[o] = h;
        Tl[o] = l;
    }
}

// ---------------------------------------------------------------------------
// Split-bf16 mma.sync GEMM (unchanged from round 4)
// ---------------------------------------------------------------------------
#define LDS 40
#define STG_A_L 10240
#define STG_B_H 20480
#define STG_B_L 30720
#define STG_SZ  40960

__global__ __launch_bounds__(256)
void mma_gemm(const __nv_bfloat16* __restrict__ Ah, const __nv_bfloat16* __restrict__ Al,
              const __nv_bfloat16* __restrict__ Bh, const __nv_bfloat16* __restrict__ Bl,
              float* __restrict__ Cf,
              __nv_bfloat16* __restrict__ Ch, __nv_bfloat16* __restrict__ Cl,
              int M, int N, int K, int split_out) {
    extern __shared__ __align__(128) char smem[];
    const int tid = threadIdx.x, lane = tid & 31, wid = tid >> 5;
    const int wm = wid >> 2, wn = wid & 3;
    const int rowA0 = blockIdx.y * 128, rowB0 = blockIdx.x * 128;
    const uint32_t sb = smem_u32(smem);
    const int nk = K >> 5;

    float acc[16][4];
#pragma unroll
    for (int i = 0; i < 16; i++)
#pragma unroll
        for (int j = 0; j < 4; j++) acc[i][j] = 0.0f;

    auto load_stage = [&](int stage, int kc) {
        const uint32_t d0 = sb + (uint32_t)stage * STG_SZ;
        const int k0 = kc * 32;
#pragma unroll
        for (int i = 0; i < 8; i++) {
            int id = tid + i * 256;
            int arr = id >> 9;
            int rem = id & 511;
            int row = rem >> 2;
            int ch  = (rem & 3) << 4;
            uint32_t dst = d0 + arr * 10240 + row * 80 + ch;
            const __nv_bfloat16* src = (arr == 0) ? Ah : (arr == 1) ? Al
                                    : (arr == 2) ? Bh : Bl;
            int grow = ((arr < 2) ? rowA0 : rowB0) + row;
            cp16(dst, (const char*)src + ((size_t)grow * K + k0) * 2 + ch);
        }
        cp_commit();
    };

    load_stage(0, 0);

    const int rA = lane & 15;
    const int cA8 = (lane >> 4) << 3;

    for (int kc = 0; kc < nk; kc++) {
        const int s = kc & 1;
        if (kc + 1 < nk) { load_stage(s ^ 1, kc + 1); cp_wait1(); }
        else             { cp_wait0(); }
        __syncthreads();

        const uint32_t base = sb + (uint32_t)s * STG_SZ;
#pragma unroll
        for (int ks = 0; ks < 32; ks += 16) {
            uint32_t a_h[4][4], b_h[2][4], b_l[2][4];
#pragma unroll
            for (int im = 0; im < 4; im++)
                ldmx4(a_h[im], base + ((64 * wm + im * 16 + rA) * LDS + ks + cA8) * 2);
#pragma unroll
            for (int jb = 0; jb < 2; jb++) {
                uint32_t boff = ((32 * wn + jb * 16 + rA) * LDS + ks + cA8) * 2;
                ldmx4(b_h[jb], base + STG_B_H + boff);
                ldmx4(b_l[jb], base + STG_B_L + boff);
            }
#pragma unroll
            for (int im = 0; im < 4; im++)
#pragma unroll
                for (int jn = 0; jn < 4; jn++) {
                    int jb = jn >> 1, sub = jn & 1;
                    mma16816(acc[im * 4 + jn], a_h[im], b_h[jb][sub], b_h[jb][sub + 2]);
                    mma16816(acc[im * 4 + jn], a_h[im], b_l[jb][sub], b_l[jb][sub + 2]);
                }
#pragma unroll
            for (int im = 0; im < 4; im++) {
                uint32_t a_l[4];
                ldmx4(a_l, base + STG_A_L + ((64 * wm + im * 16 + rA) * LDS + ks + cA8) * 2);
#pragma unroll
                for (int jn = 0; jn < 4; jn++) {
                    int jb = jn >> 1, sub = jn & 1;
                    mma16816(acc[im * 4 + jn], a_l, b_h[jb][sub], b_h[jb][sub + 2]);
                }
            }
        }
        __syncthreads();
    }

    const int er = lane >> 2, ec = (lane & 3) << 1;
#pragma unroll
    for (int im = 0; im < 4; im++) {
        int r0 = rowA0 + 64 * wm + im * 16 + er;
#pragma unroll
        for (int jn = 0; jn < 4; jn++) {
            int c = rowB0 + 32 * wn + jn * 8 + ec;
            float* a = acc[im * 4 + jn];
            if (split_out) {
                store_split2(Ch, Cl, (size_t)r0 * N + c, a[0], a[1]);
                store_split2(Ch, Cl, (size_t)(r0 + 8) * N + c, a[2], a[3]);
            } else {
                *(float2*)(Cf + (size_t)r0 * N + c) = make_float2(a[0], a[1]);
                *(float2*)(Cf + (size_t)(r0 + 8) * N + c) = make_float2(a[2], a[3]);
            }
        }
    }
}

// ---------------------------------------------------------------------------
// Register-resident FA2 flash attention (split-bf16 mma, T5 bias).
// Grid (S/128, B*H), 256 threads = 8 warps; each warp: 16 q-rows x 64 keys.
// S and P never leave registers; P packed acc->A-fragment directly.
// ---------------------------------------------------------------------------
#define LKV 72
#define AQH 0
#define AQL 18432
#define AKH 36864
#define AKL 46080
#define AVH 55296
#define AVL 64512
#define ABIAS 73728
#define ATTN_SMEM 74624
#define NKT (SS / 64)

__global__ __launch_bounds__(256, 2)
void attn_fa2(const __nv_bfloat16* __restrict__ Qh, const __nv_bfloat16* __restrict__ Ql,
              const __nv_bfloat16* __restrict__ Kh, const __nv_bfloat16* __restrict__ Kl,
              const __nv_bfloat16* __restrict__ Vh, const __nv_bfloat16* __restrict__ Vl,
              const float* __restrict__ biasTab,
              __nv_bfloat16* __restrict__ Ch, __nv_bfloat16* __restrict__ Cl) {
    extern __shared__ __align__(128) char sm[];
    const int tid = threadIdx.x, lane = tid & 31, wid = tid >> 5;
    const int qt = blockIdx.x, bhi = blockIdx.y;
    const int b = bhi >> 4, h = bhi & 15;
    const int q0 = qt * 128;
    const size_t base = (size_t)b * SS * INNER + (size_t)h * DKV;
    const float* bt = biasTab + h * NREL + (SS - 1) - q0 - 127;   // + k0 + i
    const uint32_t sb = smem_u32(sm);
    float* bias_s = (float*)(sm + ABIAS);

    const int rA = lane & 15, cA8 = (lane >> 4) << 3;
    const int er = lane >> 2, qr = (lane & 3) << 1;
    const int r0 = wid * 16 + er, r1 = r0 + 8;

    auto loadK = [&](int kt) {
        const int k0 = kt * 64;
#pragma unroll
        for (int i = 0; i < 4; i++) {
            int id = tid + i * 256;
            int arr = id >> 9, rem = id & 511;
            int row = rem >> 3, ch = (rem & 7) << 4;
            const __nv_bfloat16* src = arr ? Kl : Kh;
            cp16(sb + AKH + arr * 9216 + row * 144 + ch,
                 (const char*)src + (base + (size_t)(k0 + row) * INNER) * 2 + ch);
        }
    };
    auto loadV = [&](int kt) {
        const int k0 = kt * 64;
#pragma unroll
        for (int i = 0; i < 4; i++) {
            int id = tid + i * 256;
            int arr = id >> 9, rem = id & 511;
            int row = rem >> 3, ch = (rem & 7) << 4;
            const __nv_bfloat16* src = arr ? Vl : Vh;
            cp16(sb + AVH + arr * 9216 + row * 144 + ch,
                 (const char*)src + (base + (size_t)(k0 + row) * INNER) * 2 + ch);
        }
    };

    // Q tile (hi+lo): 128 rows x 64 cols
#pragma unroll
    for (int i = 0; i < 8; i++) {
        int id = tid + i * 256;
        int arr = id >> 10, rem = id & 1023;
        int row = rem >> 3, ch = (rem & 7) << 4;
        const __nv_bfloat16* src = arr ? Ql : Qh;
        cp16(sb + (arr ? AQL : AQH) + row * 144 + ch,
             (const char*)src + (base + (size_t)(q0 + row) * INNER) * 2 + ch);
    }
    loadK(0);
    loadV(0);
    if (tid < 191) bias_s[tid] = bt[tid];     // k0 = 0
    cp_commit();

    float m0 = -1e30f, m1 = -1e30f, l0 = 0.0f, l1 = 0.0f;
    float oac[8][4];
#pragma unroll
    for (int i = 0; i < 8; i++)
#pragma unroll
        for (int j = 0; j < 4; j++) oac[i][j] = 0.0f;

    for (int kt = 0; kt < NKT; kt++) {
        cp_wait0();
        __syncthreads();

        // ---- S = Q K^T (m16 x n64 per warp, in registers) ----
        float sac[8][4];
#pragma unroll
        for (int i = 0; i < 8; i++)
#pragma unroll
            for (int j = 0; j < 4; j++) sac[i][j] = 0.0f;
#pragma unroll
        for (int ks = 0; ks < 64; ks += 16) {
            uint32_t qfh[4], qfl[4], khf[4][4], klf[4][4];
            uint32_t aoff = ((wid * 16 + rA) * LKV + ks + cA8) * 2;
            ldmx4(qfh, sb + AQH + aoff);
            ldmx4(qfl, sb + AQL + aoff);
#pragma unroll
            for (int kb = 0; kb < 4; kb++) {
                uint32_t boff = ((16 * kb + rA) * LKV + ks + cA8) * 2;
                ldmx4(khf[kb], sb + AKH + boff);
                ldmx4(klf[kb], sb + AKL + boff);
            }
#pragma unroll
            for (int jn = 0; jn < 8; jn++) {
                int kb = jn >> 1, sub = jn & 1;
                mma16816(sac[jn], qfh, khf[kb][sub], khf[kb][sub + 2]);
                mma16816(sac[jn], qfh, klf[kb][sub], klf[kb][sub + 2]);
                mma16816(sac[jn], qfl, khf[kb][sub], khf[kb][sub + 2]);
            }
        }
        __syncthreads();                 // all warps done reading K
        if (kt + 1 < NKT) loadK(kt + 1); // overlap next-K with softmax+PV
        cp_commit();

        // ---- softmax in registers ----
        float vx0 = -1e30f, vx1 = -1e30f;
#pragma unroll
        for (int jn = 0; jn < 8; jn++) {
            int c = jn * 8 + qr;
            sac[jn][0] += bias_s[c - r0 + 127];
            sac[jn][1] += bias_s[c + 1 - r0 + 127];
            sac[jn][2] += bias_s[c - r1 + 127];
            sac[jn][3] += bias_s[c + 1 - r1 + 127];
            vx0 = fmaxf(vx0, fmaxf(sac[jn][0], sac[jn][1]));
            vx1 = fmaxf(vx1, fmaxf(sac[jn][2], sac[jn][3]));
        }
#pragma unroll
        for (int off = 1; off < 4; off <<= 1) {
            vx0 = fmaxf(vx0, __shfl_xor_sync(0xffffffffu, vx0, off));
            vx1 = fmaxf(vx1, __shfl_xor_sync(0xffffffffu, vx1, off));
        }
        float mn0 = fmaxf(m0, vx0), mn1 = fmaxf(m1, vx1);
        float al0 = __expf(m0 - mn0), al1 = __expf(m1 - mn1);
        float sum0 = 0.0f, sum1 = 0.0f;
        uint32_t pfh[4][4], pfl[4][4];
#pragma unroll
        for (int t = 0; t < 4; t++) {
#pragma unroll
            for (int half = 0; half < 2; half++) {
                int j = 2 * t + half;
                float e0 = __expf(sac[j][0] - mn0);
                float e1 = __expf(sac[j][1] - mn0);
                float e2 = __expf(sac[j][2] - mn1);
                float e3 = __expf(sac[j][3] - mn1);
                sum0 += e0 + e1;
                sum1 += e2 + e3;
                uint32_t h01 = pack_bf2(e0, e1);
                uint32_t h23 = pack_bf2(e2, e3);
                __nv_bfloat162 bh01 = *(__nv_bfloat162*)&h01;
                __nv_bfloat162 bh23 = *(__nv_bfloat162*)&h23;
                uint32_t lo01 = pack_bf2(e0 - __bfloat162float(bh01.x),
                                         e1 - __bfloat162float(bh01.y));
                uint32_t lo23 = pack_bf2(e2 - __bfloat162float(bh23.x),
                                         e3 - __bfloat162float(bh23.y));
                pfh[t][half * 2 + 0] = h01;   // a0/a2: row er,  k-cols
                pfh[t][half * 2 + 1] = h23;   // a1/a3: row er+8
                pfl[t][half * 2 + 0] = lo01;
                pfl[t][half * 2 + 1] = lo23;
            }
        }
#pragma unroll
        for (int off = 1; off < 4; off <<= 1) {
            sum0 += __shfl_xor_sync(0xffffffffu, sum0, off);
            sum1 += __shfl_xor_sync(0xffffffffu, sum1, off);
        }
        l0 = l0 * al0 + sum0; m0 = mn0;
        l1 = l1 * al1 + sum1; m1 = mn1;
#pragma unroll
        for (int jn = 0; jn < 8; jn++) {
            oac[jn][0] *= al0; oac[jn][1] *= al0;
            oac[jn][2] *= al1; oac[jn][3] *= al1;
        }

        // ---- O += P V ----
#pragma unroll
        for (int t = 0; t < 4; t++) {
            uint32_t vhf[4][4], vlf[4][4];
#pragma unroll
            for (int db = 0; db < 4; db++) {
                uint32_t voff = ((16 * t + rA) * LKV + 16 * db + cA8) * 2;
                ldmx4t(vhf[db], sb + AVH + voff);
                ldmx4t(vlf[db], sb + AVL + voff);
            }
#pragma unroll
            for (int db = 0; db < 4; db++) {
                mma16816(oac[2 * db],     pfh[t], vhf[db][0], vhf[db][1]);
                mma16816(oac[2 * db + 1], pfh[t], vhf[db][2], vhf[db][3]);
                mma16816(oac[2 * db],     pfh[t], vlf[db][0], vlf[db][1]);
                mma16816(oac[2 * db + 1], pfh[t], vlf[db][2], vlf[db][3]);
                mma16816(oac[2 * db],     pfl[t], vhf[db][0], vhf[db][1]);
                mma16816(oac[2 * db + 1], pfl[t], vhf[db][2], vhf[db][3]);
            }
        }
        __syncthreads();                 // all warps done reading V + bias
        if (kt + 1 < NKT) {
            loadV(kt + 1);
            if (tid < 191) bias_s[tid] = bt[(kt + 1) * 64 + tid];
        }
        cp_commit();
    }

    // ---- epilogue: normalize + split-bf16 store ----
    float inv0 = 1.0f / l0, inv1 = 1.0f / l1;
#pragma unroll
    for (int jn = 0; jn < 8; jn++) {
        int c = jn * 8 + qr;
        store_split2(Ch, Cl, base + (size_t)(q0 + r0) * INNER + c,
                     oac[jn][0] * inv0, oac[jn][1] * inv0);
        store_split2(Ch, Cl, base + (size_t)(q0 + r1) * INNER + c,
                     oac[jn][2] * inv1, oac[jn][3] * inv1);
    }
}

// ---------------------------------------------------------------------------
extern "C" void kernel_launch(void* const* d_in, const int* in_sizes, int n_in,
                              void* d_out, int out_size) {
    const float* hidden = (const float*)d_in[0];
    const float* Wq     = (const float*)d_in[1];
    const float* Wk     = (const float*)d_in[2];
    const float* Wv     = (const float*)d_in[3];
    const float* Wo     = (const float*)d_in[4];
    const float* rel    = (const float*)d_in[5];
    float* out = (float*)d_out;

    float* pB;
    __nv_bfloat16 *pHh, *pHl, *pQh, *pQl, *pKh, *pKl, *pVh, *pVl, *pCh, *pCl;
    __nv_bfloat16 *pWqTh, *pWqTl, *pWkTh, *pWkTl, *pWvTh, *pWvTl, *pWoTh, *pWoTl;
    cudaGetSymbolAddress((void**)&pB, g_biasTab);
    cudaGetSymbolAddress((void**)&pHh, g_Hh);
    cudaGetSymbolAddress((void**)&pHl, g_Hl);
    cudaGetSymbolAddress((void**)&pQh, g_Qh);
    cudaGetSymbolAddress((void**)&pQl, g_Ql);
    cudaGetSymbolAddress((void**)&pKh, g_Kh);
    cudaGetSymbolAddress((void**)&pKl, g_Kl);
    cudaGetSymbolAddress((void**)&pVh, g_Vh);
    cudaGetSymbolAddress((void**)&pVl, g_Vl);
    cudaGetSymbolAddress((void**)&pCh, g_Ch);
    cudaGetSymbolAddress((void**)&pCl, g_Cl);
    cudaGetSymbolAddress((void**)&pWqTh, g_WqTh);
    cudaGetSymbolAddress((void**)&pWqTl, g_WqTl);
    cudaGetSymbolAddress((void**)&pWkTh, g_WkTh);
    cudaGetSymbolAddress((void**)&pWkTl, g_WkTl);
    cudaGetSymbolAddress((void**)&pWvTh, g_WvTh);
    cudaGetSymbolAddress((void**)&pWvTl, g_WvTl);
    cudaGetSymbolAddress((void**)&pWoTh, g_WoTh);
    cudaGetSymbolAddress((void**)&pWoTl, g_WoTl);

    cudaFuncSetAttribute(mma_gemm,
                         cudaFuncAttributeMaxDynamicSharedMemorySize, 2 * STG_SZ);
    cudaFuncSetAttribute(attn_fa2,
                         cudaFuncAttributeMaxDynamicSharedMemorySize, ATTN_SMEM);

    bias_table_kernel<<<NH, 256>>>(rel, pB);

    int n4h = BS_TOT * DMODEL / 4;
    split_plain<<<n4h / 256, 256>>>(hidden, pHh, pHl, n4h);
    dim3 tgrid(DMODEL / 32, DMODEL / 32), tblk(32, 8);
    split_transpose<<<tgrid, tblk>>>(Wq, pWqTh, pWqTl, DMODEL, INNER);
    split_transpose<<<tgrid, tblk>>>(Wk, pWkTh, pWkTl, DMODEL, INNER);
    split_transpose<<<tgrid, tblk>>>(Wv, pWvTh, pWvTl, DMODEL, INNER);
    split_transpose<<<tgrid, tblk>>>(Wo, pWoTh, pWoTl, INNER, DMODEL);

    dim3 gproj(INNER / 128, BS_TOT / 128);
    mma_gemm<<<gproj, 256, 2 * STG_SZ>>>(pHh, pHl, pWqTh, pWqTl,
                                         nullptr, pQh, pQl, BS_TOT, INNER, DMODEL, 1);
    mma_gemm<<<gproj, 256, 2 * STG_SZ>>>(pHh, pHl, pWkTh, pWkTl,
                                         nullptr, pKh, pKl, BS_TOT, INNER, DMODEL, 1);
    mma_gemm<<<gproj, 256, 2 * STG_SZ>>>(pHh, pHl, pWvTh, pWvTl,
                                         nullptr, pVh, pVl, BS_TOT, INNER, DMODEL, 1);

    attn_fa2<<<dim3(SS / 128, BB * NH), 256, ATTN_SMEM>>>(
        pQh, pQl, pKh, pKl, pVh, pVl, pB, pCh, pCl);

    mma_gemm<<<dim3(DMODEL / 128, BS_TOT / 128), 256, 2 * STG_SZ>>>(
        pCh, pCl, pWoTh, pWoTl, out, nullptr, nullptr, BS_TOT, DMODEL, INNER, 0);
}